// round 6
// baseline (speedup 1.0000x reference)
#include <cuda_runtime.h>
#include <stdint.h>

#define NA 4096
#define NB 4096
#define D  256
#define H  4
#define DK 64

#define TILE 64
#define STR  68   // padded smem stride (68*4B = 272B, 16B-aligned rows, conflict-free)

#define LOG2E 1.4426950408889634f

__device__ float g_Q[(size_t)NA * D];
__device__ float g_K[(size_t)NB * D];
__device__ float g_V[(size_t)NB * D];
__device__ float g_CTX[(size_t)H * NA * DK];

__device__ __forceinline__ float ex2f(float x) {
    float y;
    asm("ex2.approx.f32 %0, %1;" : "=f"(y) : "f"(x));
    return y;
}

// ---------------------------------------------------------------------------
// Fused Q/K/V projection: dst = src @ W^T   (64x64 tile, 4x4 register tile)
// ---------------------------------------------------------------------------
__global__ __launch_bounds__(256) void proj_kernel(
    const float* __restrict__ a_z, const float* __restrict__ bv_z,
    const float* __restrict__ Wq, const float* __restrict__ Wk,
    const float* __restrict__ Wv)
{
    __shared__ float a_s[16][STR];   // [k][m]
    __shared__ float w_s[16][STR];   // [k][n]
    const int mat = blockIdx.z;
    const float* __restrict__ src = (mat == 0) ? a_z : bv_z;
    const float* __restrict__ W   = (mat == 0) ? Wq : ((mat == 1) ? Wk : Wv);
    float* dst = (mat == 0) ? g_Q : ((mat == 1) ? g_K : g_V);

    const int m0 = blockIdx.x * TILE;
    const int n0 = blockIdx.y * TILE;
    const int tid = threadIdx.x;
    const int tx = tid & 15, ty = tid >> 4;
    const int lr = tid >> 2;          // 0..63 (row within tile)
    const int lc = (tid & 3) * 4;     // 0,4,8,12 (k within 16-chunk)

    float acc[4][4] = {};

    for (int k0 = 0; k0 < D; k0 += 16) {
        float4 av = *(const float4*)(src + (size_t)(m0 + lr) * D + k0 + lc);
        float4 wv = *(const float4*)(W   + (size_t)(n0 + lr) * D + k0 + lc);
        a_s[lc + 0][lr] = av.x; a_s[lc + 1][lr] = av.y;
        a_s[lc + 2][lr] = av.z; a_s[lc + 3][lr] = av.w;
        w_s[lc + 0][lr] = wv.x; w_s[lc + 1][lr] = wv.y;
        w_s[lc + 2][lr] = wv.z; w_s[lc + 3][lr] = wv.w;
        __syncthreads();
        #pragma unroll
        for (int kk = 0; kk < 16; kk++) {
            float4 aa = *(const float4*)&a_s[kk][ty * 4];
            float4 bb = *(const float4*)&w_s[kk][tx * 4];
            float ar4[4] = {aa.x, aa.y, aa.z, aa.w};
            float br4[4] = {bb.x, bb.y, bb.z, bb.w};
            #pragma unroll
            for (int i = 0; i < 4; i++)
                #pragma unroll
                for (int j = 0; j < 4; j++)
                    acc[i][j] = fmaf(ar4[i], br4[j], acc[i][j]);
        }
        __syncthreads();
    }
    #pragma unroll
    for (int i = 0; i < 4; i++) {
        float4 o = make_float4(acc[i][0], acc[i][1], acc[i][2], acc[i][3]);
        *(float4*)(dst + (size_t)(m0 + ty * 4 + i) * D + n0 + tx * 4) = o;
    }
}

// ---------------------------------------------------------------------------
// fp32 flash attention: one CTA = (64 query rows, one head). Streams 64-col
// K/V tiles, online softmax in the log2 domain (scores pre-scaled by log2e,
// so exp() is a bare MUFU.EX2). Masked entries are exactly -10.0 after the
// reference's where(-10000)+weight+clip, and ARE included in softmax.
// Mask arrives as int32 (harness materializes jnp bool as int32).
// ---------------------------------------------------------------------------
__global__ __launch_bounds__(256) void attn_kernel(
    const float* __restrict__ weight, const int* __restrict__ mask)
{
    extern __shared__ float sm[];
    float* qs = sm;                     // [DK][STR]  d-major Q
    float* ks = qs + TILE * STR;        // [DK][STR]  d-major K
    float* vs = ks + TILE * STR;        // [TILE][STR] row-major V
    float* ps = vs + TILE * STR;        // [TILE][STR] scores / probs
    float* m_row  = ps + TILE * STR;    // [64]  (log2 domain)
    float* l_row  = m_row + TILE;       // [64]
    float* sc_row = l_row + TILE;       // [64]

    const int a0 = blockIdx.x * TILE;
    const int hh = blockIdx.y;
    const int tid = threadIdx.x;
    const int tx = tid & 15, ty = tid >> 4;

    // load Q tile, transposed to d-major
    #pragma unroll
    for (int l = 0; l < 4; l++) {
        int f = tid + l * 256;
        int r = f >> 4;
        int d4 = (f & 15) * 4;
        float4 v = *(const float4*)&g_Q[(size_t)(a0 + r) * D + hh * DK + d4];
        qs[(d4 + 0) * STR + r] = v.x;
        qs[(d4 + 1) * STR + r] = v.y;
        qs[(d4 + 2) * STR + r] = v.z;
        qs[(d4 + 3) * STR + r] = v.w;
    }
    if (tid < TILE) { m_row[tid] = -1e30f; l_row[tid] = 0.0f; }

    float O[4][4] = {};

    for (int nt = 0; nt < NB / TILE; nt++) {
        const int b0 = nt * TILE;
        __syncthreads();   // prev PV done before overwriting ks/vs/ps

        // load K (d-major) and V (row-major)
        #pragma unroll
        for (int l = 0; l < 4; l++) {
            int f = tid + l * 256;
            int c = f >> 4;
            int d4 = (f & 15) * 4;
            float4 kv = *(const float4*)&g_K[(size_t)(b0 + c) * D + hh * DK + d4];
            ks[(d4 + 0) * STR + c] = kv.x;
            ks[(d4 + 1) * STR + c] = kv.y;
            ks[(d4 + 2) * STR + c] = kv.z;
            ks[(d4 + 3) * STR + c] = kv.w;
            float4 vv = *(const float4*)&g_V[(size_t)(b0 + c) * D + hh * DK + d4];
            *(float4*)&vs[c * STR + d4] = vv;
        }
        __syncthreads();

        // S = Q K^T (4x4 register tile)
        float acc[4][4] = {};
        #pragma unroll 16
        for (int d = 0; d < DK; d++) {
            float4 qv = *(const float4*)&qs[d * STR + ty * 4];
            float4 kv = *(const float4*)&ks[d * STR + tx * 4];
            float qa[4] = {qv.x, qv.y, qv.z, qv.w};
            float kb[4] = {kv.x, kv.y, kv.z, kv.w};
            #pragma unroll
            for (int i = 0; i < 4; i++)
                #pragma unroll
                for (int j = 0; j < 4; j++)
                    acc[i][j] = fmaf(qa[i], kb[j], acc[i][j]);
        }

        // epilogue: /8 + weight, mask(int32) -> -10, clip, *log2e, write ps
        #pragma unroll
        for (int i = 0; i < 4; i++) {
            const size_t row = (size_t)(a0 + ty * 4 + i) * NB + b0 + tx * 4;
            float4 wv = *(const float4*)(weight + row);
            int4  mv = *(const int4*)(mask + row);
            float wa[4] = {wv.x, wv.y, wv.z, wv.w};
            int   ma[4] = {mv.x, mv.y, mv.z, mv.w};
            float sv[4];
            #pragma unroll
            for (int j = 0; j < 4; j++) {
                float s = fminf(fmaxf(acc[i][j] * 0.125f + wa[j], -10.0f), 10.0f);
                s = ma[j] ? s : -10.0f;
                sv[j] = s * LOG2E;
            }
            *(float4*)&ps[(ty * 4 + i) * STR + tx * 4] =
                make_float4(sv[0], sv[1], sv[2], sv[3]);
        }
        __syncthreads();

        // online softmax row update (log2 domain): 4 threads per row
        {
            const int r = tid >> 2;
            const int q = tid & 3;
            float* prow = ps + r * STR + q * 16;
            float xx[16];
            *(float4*)&xx[0]  = *(const float4*)(prow + 0);
            *(float4*)&xx[4]  = *(const float4*)(prow + 4);
            *(float4*)&xx[8]  = *(const float4*)(prow + 8);
            *(float4*)&xx[12] = *(const float4*)(prow + 12);
            float mx = -1e30f;
            #pragma unroll
            for (int e = 0; e < 16; e++) mx = fmaxf(mx, xx[e]);
            mx = fmaxf(mx, __shfl_xor_sync(0xffffffffu, mx, 1));
            mx = fmaxf(mx, __shfl_xor_sync(0xffffffffu, mx, 2));
            float mo = m_row[r];
            float mn = fmaxf(mo, mx);
            float ssum = 0.0f;
            #pragma unroll
            for (int e = 0; e < 16; e++) {
                xx[e] = ex2f(xx[e] - mn);
                ssum += xx[e];
            }
            *(float4*)(prow + 0)  = *(const float4*)&xx[0];
            *(float4*)(prow + 4)  = *(const float4*)&xx[4];
            *(float4*)(prow + 8)  = *(const float4*)&xx[8];
            *(float4*)(prow + 12) = *(const float4*)&xx[12];
            ssum += __shfl_xor_sync(0xffffffffu, ssum, 1);
            ssum += __shfl_xor_sync(0xffffffffu, ssum, 2);
            if (q == 0) {
                float sc = (mo > -1e29f) ? ex2f(mo - mn) : 0.0f;
                l_row[r] = l_row[r] * sc + ssum;
                m_row[r] = mn;
                sc_row[r] = sc;
            }
        }
        __syncthreads();

        // rescale O, then O += P V (c blocked by 4: all-LDS.128, pa broadcast)
        float scl[4];
        #pragma unroll
        for (int i = 0; i < 4; i++) scl[i] = sc_row[ty * 4 + i];
        #pragma unroll
        for (int i = 0; i < 4; i++)
            #pragma unroll
            for (int j = 0; j < 4; j++)
                O[i][j] *= scl[i];

        #pragma unroll 4
        for (int c0 = 0; c0 < TILE; c0 += 4) {
            float4 pa4[4];
            #pragma unroll
            for (int i = 0; i < 4; i++)
                pa4[i] = *(const float4*)&ps[(ty * 4 + i) * STR + c0];
            float pam[4][4] = {
                {pa4[0].x, pa4[0].y, pa4[0].z, pa4[0].w},
                {pa4[1].x, pa4[1].y, pa4[1].z, pa4[1].w},
                {pa4[2].x, pa4[2].y, pa4[2].z, pa4[2].w},
                {pa4[3].x, pa4[3].y, pa4[3].z, pa4[3].w}};
            #pragma unroll
            for (int cc = 0; cc < 4; cc++) {
                float4 vv = *(const float4*)&vs[(c0 + cc) * STR + tx * 4];
                float vb[4] = {vv.x, vv.y, vv.z, vv.w};
                #pragma unroll
                for (int i = 0; i < 4; i++)
                    #pragma unroll
                    for (int j = 0; j < 4; j++)
                        O[i][j] = fmaf(pam[i][cc], vb[j], O[i][j]);
            }
        }
    }

    // normalize and write context (l_row stable since last pre-PV barrier)
    #pragma unroll
    for (int i = 0; i < 4; i++) {
        float inv = 1.0f / l_row[ty * 4 + i];
        float4 o = make_float4(O[i][0] * inv, O[i][1] * inv,
                               O[i][2] * inv, O[i][3] * inv);
        *(float4*)&g_CTX[((size_t)hh * NA + a0 + ty * 4 + i) * DK + tx * 4] = o;
    }
}

// ---------------------------------------------------------------------------
// head mean + influence (softmax rows sum to 1 -> influence == 1.0 exactly)
// ---------------------------------------------------------------------------
__global__ void combine_kernel(float* __restrict__ out)
{
    int idx = blockIdx.x * blockDim.x + threadIdx.x;
    if (idx < NA * DK) {
        float s = g_CTX[idx] + g_CTX[NA * DK + idx] +
                  g_CTX[2 * NA * DK + idx] + g_CTX[3 * NA * DK + idx];
        out[idx] = s * 0.25f;
    }
    if (idx < NA) out[NA * DK + idx] = 1.0f;
}

// ---------------------------------------------------------------------------
extern "C" void kernel_launch(void* const* d_in, const int* in_sizes, int n_in,
                              void* d_out, int out_size)
{
    const float* a_z    = (const float*)d_in[0];
    const float* bv_z   = (const float*)d_in[1];
    const int*   mask   = (const int*)d_in[2];   // jnp bool -> int32 per harness
    const float* weight = (const float*)d_in[3];
    const float* Wq     = (const float*)d_in[4];
    const float* Wk     = (const float*)d_in[5];
    const float* Wv     = (const float*)d_in[6];
    float* out = (float*)d_out;

    const int smem = (4 * TILE * STR + 3 * TILE) * (int)sizeof(float); // 70400 B
    cudaFuncSetAttribute(attn_kernel,
                         cudaFuncAttributeMaxDynamicSharedMemorySize, smem);

    proj_kernel<<<dim3(NA / TILE, D / TILE, 3), 256>>>(a_z, bv_z, Wq, Wk, Wv);
    attn_kernel<<<dim3(NA / TILE, H), 256, smem>>>(weight, mask);
    combine_kernel<<<(NA * DK + 255) / 256, 256>>>(out);
}

// round 12
// speedup vs baseline: 2.3102x; 2.3102x over previous
#include <cuda_runtime.h>
#include <cuda_bf16.h>
#include <stdint.h>

#define NA 4096
#define NB 4096
#define D  256
#define H  4
#define DK 64

#define QM 128            // query rows per CTA
#define BN 64             // kv cols per iteration
#define NIT (NB / BN)     // 64

#define LOG2E    1.4426950408889634f
#define TENLOG2E 14.426950408889634f

#define PTILE 64
#define PSTR  68

// smem tile geometry: 64 rows x 64 bf16, row stride 72 bf16 (144 B) -> 4g+i bank-free
#define KSTR   72
#define ARRB   9216           // 64 * 144 bytes per array
#define BUFB   36864          // 4 arrays (Khi,Klo,VThi,VTlo)
#define SME_TOT (2 * BUFB)    // double buffered

// ---- device globals ------------------------------------------------------
__device__ __nv_bfloat16 g_Qhi[(size_t)NA * D], g_Qlo[(size_t)NA * D];
__device__ __nv_bfloat16 g_Khi[(size_t)NB * D], g_Klo[(size_t)NB * D];
__device__ __nv_bfloat16 g_VThi[(size_t)D * NB], g_VTlo[(size_t)D * NB];
__device__ float g_WB[(size_t)NA * NB];
__device__ float g_CTX[(size_t)H * NA * DK];

// ---- helpers -------------------------------------------------------------
__device__ __forceinline__ uint32_t smem_u32(const void* p) {
    uint32_t a;
    asm("{ .reg .u64 t; cvta.to.shared.u64 t, %1; cvt.u32.u64 %0, t; }"
        : "=r"(a) : "l"(p));
    return a;
}
__device__ __forceinline__ float ex2f(float x) {
    float y; asm("ex2.approx.f32 %0, %1;" : "=f"(y) : "f"(x)); return y;
}
__device__ __forceinline__ uint32_t lds32(uint32_t a) {
    uint32_t v; asm volatile("ld.shared.b32 %0, [%1];" : "=r"(v) : "r"(a)); return v;
}
__device__ __forceinline__ void cp16(uint32_t dst, const void* src) {
    asm volatile("cp.async.cg.shared.global [%0], [%1], 16;" :: "r"(dst), "l"(src));
}
#define CP_COMMIT() asm volatile("cp.async.commit_group;" ::: "memory")
#define CP_WAIT0()  asm volatile("cp.async.wait_group 0;" ::: "memory")

// mma.sync m16n8k16 bf16 -> f32 (baseline sm_80+ PTX; no 'a'-target needed)
__device__ __forceinline__ void hmma(float c[4],
    uint32_t a0, uint32_t a1, uint32_t a2, uint32_t a3,
    uint32_t b0, uint32_t b1)
{
    asm volatile(
        "mma.sync.aligned.m16n8k16.row.col.f32.bf16.bf16.f32 "
        "{%0,%1,%2,%3}, {%4,%5,%6,%7}, {%8,%9}, {%0,%1,%2,%3};"
        : "+f"(c[0]), "+f"(c[1]), "+f"(c[2]), "+f"(c[3])
        : "r"(a0), "r"(a1), "r"(a2), "r"(a3), "r"(b0), "r"(b1));
}

__device__ __forceinline__ uint32_t pk2(float a, float b) {
    __nv_bfloat162 t;
    t.x = __float2bfloat16_rn(a);
    t.y = __float2bfloat16_rn(b);
    return *(uint32_t*)&t;
}

// ---------------------------------------------------------------------------
// Projection: dst = src @ W^T, epilogue emits bf16 hi/lo splits.
// mat 0: Q -> g_Qhi/lo [NA][D]; 1: K -> g_Khi/lo; 2: V -> transposed g_VThi/lo [D][NB]
// ---------------------------------------------------------------------------
__global__ __launch_bounds__(256) void proj_kernel(
    const float* __restrict__ a_z, const float* __restrict__ bv_z,
    const float* __restrict__ Wq, const float* __restrict__ Wk,
    const float* __restrict__ Wv)
{
    __shared__ float a_s[16][PSTR];
    __shared__ float w_s[16][PSTR];
    const int mat = blockIdx.z;
    const float* __restrict__ src = (mat == 0) ? a_z : bv_z;
    const float* __restrict__ W   = (mat == 0) ? Wq : ((mat == 1) ? Wk : Wv);

    const int m0 = blockIdx.x * PTILE;
    const int n0 = blockIdx.y * PTILE;
    const int tid = threadIdx.x;
    const int tx = tid & 15, ty = tid >> 4;
    const int lr = tid >> 2;
    const int lc = (tid & 3) * 4;

    float acc[4][4] = {};

    for (int k0 = 0; k0 < D; k0 += 16) {
        float4 av = *(const float4*)(src + (size_t)(m0 + lr) * D + k0 + lc);
        float4 wv = *(const float4*)(W   + (size_t)(n0 + lr) * D + k0 + lc);
        a_s[lc + 0][lr] = av.x; a_s[lc + 1][lr] = av.y;
        a_s[lc + 2][lr] = av.z; a_s[lc + 3][lr] = av.w;
        w_s[lc + 0][lr] = wv.x; w_s[lc + 1][lr] = wv.y;
        w_s[lc + 2][lr] = wv.z; w_s[lc + 3][lr] = wv.w;
        __syncthreads();
        #pragma unroll
        for (int kk = 0; kk < 16; kk++) {
            float4 aa = *(const float4*)&a_s[kk][ty * 4];
            float4 bb = *(const float4*)&w_s[kk][tx * 4];
            float ar4[4] = {aa.x, aa.y, aa.z, aa.w};
            float br4[4] = {bb.x, bb.y, bb.z, bb.w};
            #pragma unroll
            for (int i = 0; i < 4; i++)
                #pragma unroll
                for (int j = 0; j < 4; j++)
                    acc[i][j] = fmaf(ar4[i], br4[j], acc[i][j]);
        }
        __syncthreads();
    }

    if (mat == 2) {
        #pragma unroll
        for (int i = 0; i < 4; i++) {
            int m = m0 + ty * 4 + i;
            #pragma unroll
            for (int j = 0; j < 4; j++) {
                int n = n0 + tx * 4 + j;
                float x = acc[i][j];
                __nv_bfloat16 h = __float2bfloat16_rn(x);
                __nv_bfloat16 l = __float2bfloat16_rn(x - __bfloat162float(h));
                g_VThi[(size_t)n * NB + m] = h;
                g_VTlo[(size_t)n * NB + m] = l;
            }
        }
    } else {
        __nv_bfloat16* dh = mat ? g_Khi : g_Qhi;
        __nv_bfloat16* dl = mat ? g_Klo : g_Qlo;
        #pragma unroll
        for (int i = 0; i < 4; i++) {
            int m = m0 + ty * 4 + i;
            size_t base = (size_t)m * D + n0 + tx * 4;
            uint32_t hp[2], lp[2];
            #pragma unroll
            for (int jj = 0; jj < 2; jj++) {
                float x0 = acc[i][2 * jj], x1 = acc[i][2 * jj + 1];
                __nv_bfloat16 h0 = __float2bfloat16_rn(x0);
                __nv_bfloat16 h1 = __float2bfloat16_rn(x1);
                float r0 = x0 - __bfloat162float(h0);
                float r1 = x1 - __bfloat162float(h1);
                __nv_bfloat162 hv; hv.x = h0; hv.y = h1;
                hp[jj] = *(uint32_t*)&hv;
                lp[jj] = pk2(r0, r1);
            }
            *(uint2*)(dh + base) = make_uint2(hp[0], hp[1]);
            *(uint2*)(dl + base) = make_uint2(lp[0], lp[1]);
        }
    }
}

// ---------------------------------------------------------------------------
// wb = mask ? weight : -1e30 (clamps to exactly -10 after clip in attention)
// ---------------------------------------------------------------------------
__global__ void wb_kernel(const int* __restrict__ mask, const float* __restrict__ w)
{
    size_t i = ((size_t)blockIdx.x * blockDim.x + threadIdx.x) * 4;
    int4 m = *(const int4*)(mask + i);
    float4 wv = *(const float4*)(w + i);
    float4 o;
    o.x = m.x ? wv.x : -1e30f;
    o.y = m.y ? wv.y : -1e30f;
    o.z = m.z ? wv.z : -1e30f;
    o.w = m.w ? wv.w : -1e30f;
    *(float4*)(g_WB + i) = o;
}

// ---------------------------------------------------------------------------
// HMMA flash attention. CTA = 128 q rows x 1 head, 256 threads (8 warps x m16).
// Split-bf16: QK^T and PV each use 3 mma.sync per chunk (hi*hi + hi*lo + lo*hi).
// Fixed softmax max = 10 (scores clipped to [-10,10]) -> no online rescaling;
// O accumulates in registers across all 64 kv tiles. cp.async double buffer.
// ---------------------------------------------------------------------------
__device__ __forceinline__ void cpload(uint32_t smb, int buf, int b0, int hh, int tid)
{
    const uint32_t dstb = smb + buf * BUFB;
    #pragma unroll
    for (int u = 0; u < 8; u++) {
        int f = tid + u * 256;            // 0..2047
        int arr = f >> 9;                 // 0..3 (compile-time per u pair)
        int r = (f >> 3) & 63;
        int j = f & 7;
        const __nv_bfloat16* s;
        if (arr == 0)      s = g_Khi  + (size_t)(b0 + r) * D + hh * DK + j * 8;
        else if (arr == 1) s = g_Klo  + (size_t)(b0 + r) * D + hh * DK + j * 8;
        else if (arr == 2) s = g_VThi + (size_t)(hh * DK + r) * NB + b0 + j * 8;
        else               s = g_VTlo + (size_t)(hh * DK + r) * NB + b0 + j * 8;
        cp16(dstb + arr * ARRB + r * 144 + j * 16, s);
    }
}

__global__ __launch_bounds__(256) void attn_kernel()
{
    extern __shared__ uint8_t sm[];
    const uint32_t smb = smem_u32(sm);
    const int tid = threadIdx.x;
    const int w = tid >> 5;
    const int lane = tid & 31;
    const int g = lane >> 2;          // 0..7
    const int i4 = lane & 3;          // 0..3
    const int a0 = blockIdx.x * QM;
    const int hh = blockIdx.y;
    const int qr0 = a0 + w * 16 + g;
    const int qr1 = qr0 + 8;

    // Q A-fragments (held in registers for all 64 iterations)
    uint32_t qa[2][4][4];
    #pragma unroll
    for (int sp = 0; sp < 2; sp++) {
        const __nv_bfloat16* Qs = sp ? g_Qlo : g_Qhi;
        const __nv_bfloat16* q0 = Qs + (size_t)qr0 * D + hh * DK;
        const __nv_bfloat16* q1 = Qs + (size_t)qr1 * D + hh * DK;
        #pragma unroll
        for (int kc = 0; kc < 4; kc++) {
            qa[sp][kc][0] = *(const uint32_t*)(q0 + kc * 16 + 2 * i4);
            qa[sp][kc][1] = *(const uint32_t*)(q1 + kc * 16 + 2 * i4);
            qa[sp][kc][2] = *(const uint32_t*)(q0 + kc * 16 + 8 + 2 * i4);
            qa[sp][kc][3] = *(const uint32_t*)(q1 + kc * 16 + 8 + 2 * i4);
        }
    }

    cpload(smb, 0, 0, hh, tid);
    CP_COMMIT();

    float oc[8][4] = {};
    float lsum0 = 0.0f, lsum1 = 0.0f;

    for (int nt = 0; nt < NIT; nt++) {
        CP_WAIT0();
        __syncthreads();
        if (nt + 1 < NIT) { cpload(smb, (nt + 1) & 1, (nt + 1) * BN, hh, tid); CP_COMMIT(); }

        const uint32_t B  = smb + (nt & 1) * BUFB;
        const uint32_t KH = B, KL = B + ARRB, VH = B + 2 * ARRB, VL = B + 3 * ARRB;

        // ---- S = Q K^T (3 split MMAs per chunk) ----
        float sc[8][4];
        #pragma unroll
        for (int n = 0; n < 8; n++)
            #pragma unroll
            for (int c = 0; c < 4; c++) sc[n][c] = 0.0f;

        #pragma unroll
        for (int kc = 0; kc < 4; kc++) {
            #pragma unroll
            for (int n = 0; n < 8; n++) {
                uint32_t ro = (uint32_t)((n * 8 + g) * 144 + kc * 32 + i4 * 4);
                uint32_t kh0 = lds32(KH + ro), kh1 = lds32(KH + ro + 16);
                uint32_t kl0 = lds32(KL + ro), kl1 = lds32(KL + ro + 16);
                hmma(sc[n], qa[0][kc][0], qa[0][kc][1], qa[0][kc][2], qa[0][kc][3], kh0, kh1);
                hmma(sc[n], qa[0][kc][0], qa[0][kc][1], qa[0][kc][2], qa[0][kc][3], kl0, kl1);
                hmma(sc[n], qa[1][kc][0], qa[1][kc][1], qa[1][kc][2], qa[1][kc][3], kh0, kh1);
            }
        }

        // ---- epilogue: s/8 + wb, clip, p = 2^(s*log2e - 10*log2e), split P ----
        uint32_t ph01[8], ph23[8], pl01[8], pl23[8];
        const float* w0p = g_WB + (size_t)qr0 * NB + nt * BN + 2 * i4;
        const float* w1p = g_WB + (size_t)qr1 * NB + nt * BN + 2 * i4;
        #pragma unroll
        for (int n = 0; n < 8; n++) {
            float2 w0 = *(const float2*)(w0p + n * 8);
            float2 w1 = *(const float2*)(w1p + n * 8);
            float s0 = fminf(fmaxf(fmaf(sc[n][0], 0.125f, w0.x), -10.0f), 10.0f);
            float s1 = fminf(fmaxf(fmaf(sc[n][1], 0.125f, w0.y), -10.0f), 10.0f);
            float s2 = fminf(fmaxf(fmaf(sc[n][2], 0.125f, w1.x), -10.0f), 10.0f);
            float s3 = fminf(fmaxf(fmaf(sc[n][3], 0.125f, w1.y), -10.0f), 10.0f);
            float p0 = ex2f(fmaf(s0, LOG2E, -TENLOG2E));
            float p1 = ex2f(fmaf(s1, LOG2E, -TENLOG2E));
            float p2 = ex2f(fmaf(s2, LOG2E, -TENLOG2E));
            float p3 = ex2f(fmaf(s3, LOG2E, -TENLOG2E));
            lsum0 += p0 + p1;
            lsum1 += p2 + p3;
            __nv_bfloat16 h0 = __float2bfloat16_rn(p0);
            __nv_bfloat16 h1 = __float2bfloat16_rn(p1);
            __nv_bfloat16 h2 = __float2bfloat16_rn(p2);
            __nv_bfloat16 h3 = __float2bfloat16_rn(p3);
            { __nv_bfloat162 t; t.x = h0; t.y = h1; ph01[n] = *(uint32_t*)&t; }
            { __nv_bfloat162 t; t.x = h2; t.y = h3; ph23[n] = *(uint32_t*)&t; }
            pl01[n] = pk2(p0 - __bfloat162float(h0), p1 - __bfloat162float(h1));
            pl23[n] = pk2(p2 - __bfloat162float(h2), p3 - __bfloat162float(h3));
        }

        // ---- O += P V (A-frags come straight from acc layout, zero shuffles) ----
        #pragma unroll
        for (int kc = 0; kc < 4; kc++) {
            uint32_t ah0 = ph01[2 * kc], ah1 = ph23[2 * kc];
            uint32_t ah2 = ph01[2 * kc + 1], ah3 = ph23[2 * kc + 1];
            uint32_t al0 = pl01[2 * kc], al1 = pl23[2 * kc];
            uint32_t al2 = pl01[2 * kc + 1], al3 = pl23[2 * kc + 1];
            #pragma unroll
            for (int nd = 0; nd < 8; nd++) {
                uint32_t ro = (uint32_t)((nd * 8 + g) * 144 + kc * 32 + i4 * 4);
                uint32_t vh0 = lds32(VH + ro), vh1 = lds32(VH + ro + 16);
                uint32_t vl0 = lds32(VL + ro), vl1 = lds32(VL + ro + 16);
                hmma(oc[nd], ah0, ah1, ah2, ah3, vh0, vh1);
                hmma(oc[nd], al0, al1, al2, al3, vh0, vh1);
                hmma(oc[nd], ah0, ah1, ah2, ah3, vl0, vl1);
            }
        }
    }

    // ---- finalize: reduce lsum across quad, normalize, store ----
    lsum0 += __shfl_xor_sync(0xffffffffu, lsum0, 1);
    lsum0 += __shfl_xor_sync(0xffffffffu, lsum0, 2);
    lsum1 += __shfl_xor_sync(0xffffffffu, lsum1, 1);
    lsum1 += __shfl_xor_sync(0xffffffffu, lsum1, 2);
    const float inv0 = 1.0f / lsum0;
    const float inv1 = 1.0f / lsum1;

    float* d0 = g_CTX + ((size_t)hh * NA + qr0) * DK;
    float* d1 = g_CTX + ((size_t)hh * NA + qr1) * DK;
    #pragma unroll
    for (int nd = 0; nd < 8; nd++) {
        *(float2*)(d0 + nd * 8 + 2 * i4) = make_float2(oc[nd][0] * inv0, oc[nd][1] * inv0);
        *(float2*)(d1 + nd * 8 + 2 * i4) = make_float2(oc[nd][2] * inv1, oc[nd][3] * inv1);
    }
}

// ---------------------------------------------------------------------------
// head mean + influence (softmax rows sum to 1 -> influence == 1.0 exactly)
// ---------------------------------------------------------------------------
__global__ void combine_kernel(float* __restrict__ out)
{
    int idx = blockIdx.x * blockDim.x + threadIdx.x;
    if (idx < NA * DK) {
        float s = g_CTX[idx] + g_CTX[NA * DK + idx] +
                  g_CTX[2 * NA * DK + idx] + g_CTX[3 * NA * DK + idx];
        out[idx] = s * 0.25f;
    }
    if (idx < NA) out[NA * DK + idx] = 1.0f;
}

// ---------------------------------------------------------------------------
extern "C" void kernel_launch(void* const* d_in, const int* in_sizes, int n_in,
                              void* d_out, int out_size)
{
    const float* a_z    = (const float*)d_in[0];
    const float* bv_z   = (const float*)d_in[1];
    const int*   mask   = (const int*)d_in[2];   // jnp bool -> int32 per harness
    const float* weight = (const float*)d_in[3];
    const float* Wq     = (const float*)d_in[4];
    const float* Wk     = (const float*)d_in[5];
    const float* Wv     = (const float*)d_in[6];
    float* out = (float*)d_out;

    cudaFuncSetAttribute(attn_kernel,
                         cudaFuncAttributeMaxDynamicSharedMemorySize, SME_TOT);

    proj_kernel<<<dim3(NA / PTILE, D / PTILE, 3), 256>>>(a_z, bv_z, Wq, Wk, Wv);
    wb_kernel<<<(NA * (size_t)NB) / (256 * 4), 256>>>(mask, weight);
    attn_kernel<<<dim3(NA / QM, H), 256, SME_TOT>>>();
    combine_kernel<<<(NA * DK + 255) / 256, 256>>>(out);
}

// round 13
// speedup vs baseline: 2.4303x; 1.0520x over previous
#include <cuda_runtime.h>
#include <cuda_bf16.h>
#include <stdint.h>

#define NA 4096
#define NB 4096
#define D  256
#define H  4
#define DK 64

#define QM 128            // query rows per CTA
#define BN 64             // kv cols per iteration
#define NIT (NB / BN)     // 64

#define LOG2E    1.4426950408889634f
#define TENLOG2E 14.426950408889634f

#define PTILE 64
#define PSTR  68

// smem tile geometry: 64 rows x 64 bf16, row stride 72 bf16 (144 B)
#define KSTR   72
#define ARRB   9216           // 64 * 144 bytes per array
#define BUFB   36864          // 4 arrays (Khi,Klo,VThi,VTlo)
#define SME_TOT (2 * BUFB)    // double buffered

// ---- device globals ------------------------------------------------------
__device__ __nv_bfloat16 g_Qhi[(size_t)NA * D], g_Qlo[(size_t)NA * D];
__device__ __nv_bfloat16 g_Khi[(size_t)NB * D], g_Klo[(size_t)NB * D];
__device__ __nv_bfloat16 g_VThi[(size_t)D * NB], g_VTlo[(size_t)D * NB];
__device__ float g_WB[(size_t)NA * NB];
__device__ float g_CTX[(size_t)H * NA * DK];

// ---- helpers -------------------------------------------------------------
__device__ __forceinline__ uint32_t smem_u32(const void* p) {
    uint32_t a;
    asm("{ .reg .u64 t; cvta.to.shared.u64 t, %1; cvt.u32.u64 %0, t; }"
        : "=r"(a) : "l"(p));
    return a;
}
__device__ __forceinline__ float ex2f(float x) {
    float y; asm("ex2.approx.f32 %0, %1;" : "=f"(y) : "f"(x)); return y;
}
__device__ __forceinline__ void cp16(uint32_t dst, const void* src) {
    asm volatile("cp.async.cg.shared.global [%0], [%1], 16;" :: "r"(dst), "l"(src));
}
#define CP_COMMIT() asm volatile("cp.async.commit_group;" ::: "memory")
#define CP_WAIT0()  asm volatile("cp.async.wait_group 0;" ::: "memory")

// ldmatrix x4: 4 8x8 b16 tiles. Lane l supplies row address of tile l>>3.
__device__ __forceinline__ void ldsm4(uint32_t d[4], uint32_t a) {
    asm volatile("ldmatrix.sync.aligned.m8n8.x4.shared.b16 {%0,%1,%2,%3}, [%4];"
        : "=r"(d[0]), "=r"(d[1]), "=r"(d[2]), "=r"(d[3]) : "r"(a));
}

// mma.sync m16n8k16 bf16 -> f32 (baseline sm_80+ PTX)
__device__ __forceinline__ void hmma(float c[4],
    uint32_t a0, uint32_t a1, uint32_t a2, uint32_t a3,
    uint32_t b0, uint32_t b1)
{
    asm volatile(
        "mma.sync.aligned.m16n8k16.row.col.f32.bf16.bf16.f32 "
        "{%0,%1,%2,%3}, {%4,%5,%6,%7}, {%8,%9}, {%0,%1,%2,%3};"
        : "+f"(c[0]), "+f"(c[1]), "+f"(c[2]), "+f"(c[3])
        : "r"(a0), "r"(a1), "r"(a2), "r"(a3), "r"(b0), "r"(b1));
}

// pack {lo=a, hi=b} as bf16x2
__device__ __forceinline__ uint32_t cvt2(float a, float b) {
    uint32_t r;
    asm("cvt.rn.bf16x2.f32 %0, %1, %2;" : "=r"(r) : "f"(b), "f"(a));
    return r;
}
__device__ __forceinline__ uint32_t pk2(float a, float b) { return cvt2(a, b); }

// ---------------------------------------------------------------------------
// Projection: dst = src @ W^T, epilogue emits bf16 hi/lo splits.
// mat 0: Q -> g_Qhi/lo [NA][D]; 1: K -> g_Khi/lo; 2: V -> transposed g_VThi/lo [D][NB]
// ---------------------------------------------------------------------------
__global__ __launch_bounds__(256) void proj_kernel(
    const float* __restrict__ a_z, const float* __restrict__ bv_z,
    const float* __restrict__ Wq, const float* __restrict__ Wk,
    const float* __restrict__ Wv)
{
    __shared__ float a_s[16][PSTR];
    __shared__ float w_s[16][PSTR];
    const int mat = blockIdx.z;
    const float* __restrict__ src = (mat == 0) ? a_z : bv_z;
    const float* __restrict__ W   = (mat == 0) ? Wq : ((mat == 1) ? Wk : Wv);

    const int m0 = blockIdx.x * PTILE;
    const int n0 = blockIdx.y * PTILE;
    const int tid = threadIdx.x;
    const int tx = tid & 15, ty = tid >> 4;
    const int lr = tid >> 2;
    const int lc = (tid & 3) * 4;

    float acc[4][4] = {};

    for (int k0 = 0; k0 < D; k0 += 16) {
        float4 av = *(const float4*)(src + (size_t)(m0 + lr) * D + k0 + lc);
        float4 wv = *(const float4*)(W   + (size_t)(n0 + lr) * D + k0 + lc);
        a_s[lc + 0][lr] = av.x; a_s[lc + 1][lr] = av.y;
        a_s[lc + 2][lr] = av.z; a_s[lc + 3][lr] = av.w;
        w_s[lc + 0][lr] = wv.x; w_s[lc + 1][lr] = wv.y;
        w_s[lc + 2][lr] = wv.z; w_s[lc + 3][lr] = wv.w;
        __syncthreads();
        #pragma unroll
        for (int kk = 0; kk < 16; kk++) {
            float4 aa = *(const float4*)&a_s[kk][ty * 4];
            float4 bb = *(const float4*)&w_s[kk][tx * 4];
            float ar4[4] = {aa.x, aa.y, aa.z, aa.w};
            float br4[4] = {bb.x, bb.y, bb.z, bb.w};
            #pragma unroll
            for (int i = 0; i < 4; i++)
                #pragma unroll
                for (int j = 0; j < 4; j++)
                    acc[i][j] = fmaf(ar4[i], br4[j], acc[i][j]);
        }
        __syncthreads();
    }

    if (mat == 2) {
        #pragma unroll
        for (int i = 0; i < 4; i++) {
            int m = m0 + ty * 4 + i;
            #pragma unroll
            for (int j = 0; j < 4; j++) {
                int n = n0 + tx * 4 + j;
                float x = acc[i][j];
                __nv_bfloat16 h = __float2bfloat16_rn(x);
                __nv_bfloat16 l = __float2bfloat16_rn(x - __bfloat162float(h));
                g_VThi[(size_t)n * NB + m] = h;
                g_VTlo[(size_t)n * NB + m] = l;
            }
        }
    } else {
        __nv_bfloat16* dh = mat ? g_Khi : g_Qhi;
        __nv_bfloat16* dl = mat ? g_Klo : g_Qlo;
        #pragma unroll
        for (int i = 0; i < 4; i++) {
            int m = m0 + ty * 4 + i;
            size_t base = (size_t)m * D + n0 + tx * 4;
            uint32_t hp[2], lp[2];
            #pragma unroll
            for (int jj = 0; jj < 2; jj++) {
                float x0 = acc[i][2 * jj], x1 = acc[i][2 * jj + 1];
                uint32_t h = cvt2(x0, x1);
                float h0f = __uint_as_float(h << 16);
                float h1f = __uint_as_float(h & 0xffff0000u);
                hp[jj] = h;
                lp[jj] = cvt2(x0 - h0f, x1 - h1f);
            }
            *(uint2*)(dh + base) = make_uint2(hp[0], hp[1]);
            *(uint2*)(dl + base) = make_uint2(lp[0], lp[1]);
        }
    }
}

// ---------------------------------------------------------------------------
// wb = mask ? weight : -1e30 (clamps to exactly -10 after clip in attention)
// ---------------------------------------------------------------------------
__global__ void wb_kernel(const int* __restrict__ mask, const float* __restrict__ w)
{
    size_t i = ((size_t)blockIdx.x * blockDim.x + threadIdx.x) * 4;
    int4 m = *(const int4*)(mask + i);
    float4 wv = *(const float4*)(w + i);
    float4 o;
    o.x = m.x ? wv.x : -1e30f;
    o.y = m.y ? wv.y : -1e30f;
    o.z = m.z ? wv.z : -1e30f;
    o.w = m.w ? wv.w : -1e30f;
    *(float4*)(g_WB + i) = o;
}

// ---------------------------------------------------------------------------
// HMMA flash attention. CTA = 128 q rows x 1 head, 256 threads (8 warps x m16).
// Split-bf16: QK^T and PV each use 3 mma.sync per chunk (hi*hi + hi*lo + lo*hi).
// Fixed softmax max = 10 -> no online rescaling; O accumulates in registers.
// cp.async double buffer; B-fragments via ldmatrix.x4.
// ---------------------------------------------------------------------------
__device__ __forceinline__ void cpload(uint32_t smb, int buf, int b0, int hh, int tid)
{
    const uint32_t dstb = smb + buf * BUFB;
    #pragma unroll
    for (int u = 0; u < 8; u++) {
        int f = tid + u * 256;            // 0..2047
        int arr = f >> 9;                 // 0..3
        int r = (f >> 3) & 63;
        int j = f & 7;
        const __nv_bfloat16* s;
        if (arr == 0)      s = g_Khi  + (size_t)(b0 + r) * D + hh * DK + j * 8;
        else if (arr == 1) s = g_Klo  + (size_t)(b0 + r) * D + hh * DK + j * 8;
        else if (arr == 2) s = g_VThi + (size_t)(hh * DK + r) * NB + b0 + j * 8;
        else               s = g_VTlo + (size_t)(hh * DK + r) * NB + b0 + j * 8;
        cp16(dstb + arr * ARRB + r * 144 + j * 16, s);
    }
}

__global__ __launch_bounds__(256) void attn_kernel()
{
    extern __shared__ uint8_t sm[];
    const uint32_t smb = smem_u32(sm);
    const int tid = threadIdx.x;
    const int w = tid >> 5;
    const int lane = tid & 31;
    const int g = lane >> 2;          // 0..7
    const int i4 = lane & 3;          // 0..3
    const int a0 = blockIdx.x * QM;
    const int hh = blockIdx.y;
    const int qr0 = a0 + w * 16 + g;
    const int qr1 = qr0 + 8;

    // per-thread ldmatrix row offset: tile m = lane>>3, row r = lane&7
    // addr = base + (p*16 + (m>>1)*8 + r)*144 + kc*32 + (m&1)*16
    const int lm = lane >> 3;
    const uint32_t rb144 = (uint32_t)(((lm >> 1) * 8 + (lane & 7)) * 144 + (lm & 1) * 16);

    // Q A-fragments (held in registers for all 64 iterations)
    uint32_t qa[2][4][4];
    #pragma unroll
    for (int sp = 0; sp < 2; sp++) {
        const __nv_bfloat16* Qs = sp ? g_Qlo : g_Qhi;
        const __nv_bfloat16* q0 = Qs + (size_t)qr0 * D + hh * DK;
        const __nv_bfloat16* q1 = Qs + (size_t)qr1 * D + hh * DK;
        #pragma unroll
        for (int kc = 0; kc < 4; kc++) {
            qa[sp][kc][0] = *(const uint32_t*)(q0 + kc * 16 + 2 * i4);
            qa[sp][kc][1] = *(const uint32_t*)(q1 + kc * 16 + 2 * i4);
            qa[sp][kc][2] = *(const uint32_t*)(q0 + kc * 16 + 8 + 2 * i4);
            qa[sp][kc][3] = *(const uint32_t*)(q1 + kc * 16 + 8 + 2 * i4);
        }
    }

    cpload(smb, 0, 0, hh, tid);
    CP_COMMIT();

    float oc[8][4] = {};
    float lsum0 = 0.0f, lsum1 = 0.0f;

    const float* w0base = g_WB + (size_t)qr0 * NB + 2 * i4;
    const float* w1base = g_WB + (size_t)qr1 * NB + 2 * i4;

    for (int nt = 0; nt < NIT; nt++) {
        // prefetch wb for this tile FIRST so latency overlaps the MMA phase
        float2 wv0[8], wv1[8];
        {
            const float* w0p = w0base + nt * BN;
            const float* w1p = w1base + nt * BN;
            #pragma unroll
            for (int n = 0; n < 8; n++) {
                wv0[n] = *(const float2*)(w0p + n * 8);
                wv1[n] = *(const float2*)(w1p + n * 8);
            }
        }

        CP_WAIT0();
        __syncthreads();
        if (nt + 1 < NIT) { cpload(smb, (nt + 1) & 1, (nt + 1) * BN, hh, tid); CP_COMMIT(); }

        const uint32_t B  = smb + (nt & 1) * BUFB;
        const uint32_t KH = B + rb144, KL = B + ARRB + rb144;
        const uint32_t VH = B + 2 * ARRB + rb144, VL = B + 3 * ARRB + rb144;

        // ---- S = Q K^T (3 split MMAs per chunk; B-frags via ldmatrix.x4) ----
        float sc[8][4];
        #pragma unroll
        for (int n = 0; n < 8; n++)
            #pragma unroll
            for (int c = 0; c < 4; c++) sc[n][c] = 0.0f;

        #pragma unroll
        for (int kc = 0; kc < 4; kc++) {
            #pragma unroll
            for (int p = 0; p < 4; p++) {
                uint32_t off = (uint32_t)(p * 2304 + kc * 32);
                uint32_t kh[4], kl[4];
                ldsm4(kh, KH + off);
                ldsm4(kl, KL + off);
                int n0 = 2 * p, n1 = 2 * p + 1;
                hmma(sc[n0], qa[0][kc][0], qa[0][kc][1], qa[0][kc][2], qa[0][kc][3], kh[0], kh[1]);
                hmma(sc[n0], qa[0][kc][0], qa[0][kc][1], qa[0][kc][2], qa[0][kc][3], kl[0], kl[1]);
                hmma(sc[n0], qa[1][kc][0], qa[1][kc][1], qa[1][kc][2], qa[1][kc][3], kh[0], kh[1]);
                hmma(sc[n1], qa[0][kc][0], qa[0][kc][1], qa[0][kc][2], qa[0][kc][3], kh[2], kh[3]);
                hmma(sc[n1], qa[0][kc][0], qa[0][kc][1], qa[0][kc][2], qa[0][kc][3], kl[2], kl[3]);
                hmma(sc[n1], qa[1][kc][0], qa[1][kc][1], qa[1][kc][2], qa[1][kc][3], kh[2], kh[3]);
            }
        }

        // ---- epilogue: s/8 + wb, clip, p = 2^(s*log2e - 10*log2e), split P ----
        uint32_t ph01[8], ph23[8], pl01[8], pl23[8];
        #pragma unroll
        for (int n = 0; n < 8; n++) {
            float s0 = fminf(fmaxf(fmaf(sc[n][0], 0.125f, wv0[n].x), -10.0f), 10.0f);
            float s1 = fminf(fmaxf(fmaf(sc[n][1], 0.125f, wv0[n].y), -10.0f), 10.0f);
            float s2 = fminf(fmaxf(fmaf(sc[n][2], 0.125f, wv1[n].x), -10.0f), 10.0f);
            float s3 = fminf(fmaxf(fmaf(sc[n][3], 0.125f, wv1[n].y), -10.0f), 10.0f);
            float p0 = ex2f(fmaf(s0, LOG2E, -TENLOG2E));
            float p1 = ex2f(fmaf(s1, LOG2E, -TENLOG2E));
            float p2 = ex2f(fmaf(s2, LOG2E, -TENLOG2E));
            float p3 = ex2f(fmaf(s3, LOG2E, -TENLOG2E));
            lsum0 += p0 + p1;
            lsum1 += p2 + p3;
            uint32_t h01 = cvt2(p0, p1);
            uint32_t h23 = cvt2(p2, p3);
            ph01[n] = h01; ph23[n] = h23;
            pl01[n] = cvt2(p0 - __uint_as_float(h01 << 16),
                           p1 - __uint_as_float(h01 & 0xffff0000u));
            pl23[n] = cvt2(p2 - __uint_as_float(h23 << 16),
                           p3 - __uint_as_float(h23 & 0xffff0000u));
        }

        // ---- O += P V (A-frags from acc layout; B-frags via ldmatrix.x4) ----
        #pragma unroll
        for (int kc = 0; kc < 4; kc++) {
            uint32_t ah0 = ph01[2 * kc], ah1 = ph23[2 * kc];
            uint32_t ah2 = ph01[2 * kc + 1], ah3 = ph23[2 * kc + 1];
            uint32_t al0 = pl01[2 * kc], al1 = pl23[2 * kc];
            uint32_t al2 = pl01[2 * kc + 1], al3 = pl23[2 * kc + 1];
            #pragma unroll
            for (int p = 0; p < 4; p++) {
                uint32_t off = (uint32_t)(p * 2304 + kc * 32);
                uint32_t vh[4], vl[4];
                ldsm4(vh, VH + off);
                ldsm4(vl, VL + off);
                int d0i = 2 * p, d1i = 2 * p + 1;
                hmma(oc[d0i], ah0, ah1, ah2, ah3, vh[0], vh[1]);
                hmma(oc[d0i], al0, al1, al2, al3, vh[0], vh[1]);
                hmma(oc[d0i], ah0, ah1, ah2, ah3, vl[0], vl[1]);
                hmma(oc[d1i], ah0, ah1, ah2, ah3, vh[2], vh[3]);
                hmma(oc[d1i], al0, al1, al2, al3, vh[2], vh[3]);
                hmma(oc[d1i], ah0, ah1, ah2, ah3, vl[2], vl[3]);
            }
        }
    }

    // ---- finalize: reduce lsum across quad, normalize, store ----
    lsum0 += __shfl_xor_sync(0xffffffffu, lsum0, 1);
    lsum0 += __shfl_xor_sync(0xffffffffu, lsum0, 2);
    lsum1 += __shfl_xor_sync(0xffffffffu, lsum1, 1);
    lsum1 += __shfl_xor_sync(0xffffffffu, lsum1, 2);
    const float inv0 = 1.0f / lsum0;
    const float inv1 = 1.0f / lsum1;

    float* d0 = g_CTX + ((size_t)hh * NA + qr0) * DK;
    float* d1 = g_CTX + ((size_t)hh * NA + qr1) * DK;
    #pragma unroll
    for (int nd = 0; nd < 8; nd++) {
        *(float2*)(d0 + nd * 8 + 2 * i4) = make_float2(oc[nd][0] * inv0, oc[nd][1] * inv0);
        *(float2*)(d1 + nd * 8 + 2 * i4) = make_float2(oc[nd][2] * inv1, oc[nd][3] * inv1);
    }
}

// ---------------------------------------------------------------------------
// head mean + influence (softmax rows sum to 1 -> influence == 1.0 exactly)
// ---------------------------------------------------------------------------
__global__ void combine_kernel(float* __restrict__ out)
{
    int idx = blockIdx.x * blockDim.x + threadIdx.x;
    if (idx < NA * DK) {
        float s = g_CTX[idx] + g_CTX[NA * DK + idx] +
                  g_CTX[2 * NA * DK + idx] + g_CTX[3 * NA * DK + idx];
        out[idx] = s * 0.25f;
    }
    if (idx < NA) out[NA * DK + idx] = 1.0f;
}

// ---------------------------------------------------------------------------
extern "C" void kernel_launch(void* const* d_in, const int* in_sizes, int n_in,
                              void* d_out, int out_size)
{
    const float* a_z    = (const float*)d_in[0];
    const float* bv_z   = (const float*)d_in[1];
    const int*   mask   = (const int*)d_in[2];   // jnp bool -> int32 per harness
    const float* weight = (const float*)d_in[3];
    const float* Wq     = (const float*)d_in[4];
    const float* Wk     = (const float*)d_in[5];
    const float* Wv     = (const float*)d_in[6];
    float* out = (float*)d_out;

    cudaFuncSetAttribute(attn_kernel,
                         cudaFuncAttributeMaxDynamicSharedMemorySize, SME_TOT);

    proj_kernel<<<dim3(NA / PTILE, D / PTILE, 3), 256>>>(a_z, bv_z, Wq, Wk, Wv);
    wb_kernel<<<(NA * (size_t)NB) / (256 * 4), 256>>>(mask, weight);
    attn_kernel<<<dim3(NA / QM, H), 256, SME_TOT>>>();
    combine_kernel<<<(NA * DK + 255) / 256, 256>>>(out);
}